// round 16
// baseline (speedup 1.0000x reference)
#include <cuda_runtime.h>

#define CHANNELS  8
#define IN_CH     8
#define NPARAMS   169      // 80 + 64 + 8 + 8 + 8 + 1
#define H_        128
#define W_        192
#define HW_       (H_ * W_)
#define GI        4        // instances per block
#define SW        16       // column-strip width per block (4 strips of 4 px)

typedef unsigned long long u64;

// ---- packed fp32x2 helpers (Blackwell) -------------------------------------
__device__ __forceinline__ u64 fma2(u64 a, u64 b, u64 c) {
    u64 d;
    asm("fma.rn.f32x2 %0, %1, %2, %3;" : "=l"(d) : "l"(a), "l"(b), "l"(c));
    return d;
}
__device__ __forceinline__ u64 pack2(float lo, float hi) {
    u64 d;
    asm("mov.b64 %0, {%1, %2};" : "=l"(d) : "f"(lo), "f"(hi));
    return d;
}
__device__ __forceinline__ void unpack2(u64 v, float& lo, float& hi) {
    asm("mov.b64 {%0, %1}, %2;" : "=f"(lo), "=f"(hi) : "l"(v));
}
__device__ __forceinline__ u64 relu2(u64 v) {
    float lo, hi;
    unpack2(v, lo, hi);
    return pack2(fmaxf(lo, 0.0f), fmaxf(hi, 0.0f));
}

// ---------------------------------------------------------------------------
// Single fused kernel: MLP + full aligned-2x upsample, column-strip tiling.
// Block = 16-col strip x ALL 128 logit rows, GI instances, 192 threads.
// Per instance g (3 compute iterations of 192 units = 576 units exactly):
//   units   0..511: main 4-px MLP (row = u>>2, strip = u&3) -> st[row][16]
//   units 512..575: left-halo column (col c0-1, clamped), 2 rows packed per
//                   unit -> sthalo[128]
// After sync, emit phase (512 units): each unit writes output rows 2r and
// 2r+1 for its 4 columns. Up-neighbor (row r-1) and left-neighbor (col-1)
// are both in shared memory -> no second kernel, no g_logits.
// Upsample identities (r-1, c-1 clamped at 0):
//   O[2r,  2c  ] = 0.25*(L[r-1,c-1] + L[r-1,c] + L[r,c-1] + L[r,c])
//   O[2r,  2c+1] = 0.5 *(L[r-1,c]   + L[r,c])
//   O[2r+1,2c  ] = 0.5 *(L[r,c-1]   + L[r,c])
//   O[2r+1,2c+1] =       L[r,c]
// ---------------------------------------------------------------------------
__global__ __launch_bounds__(192)
void fused_mask_kernel(const float* __restrict__ mask_feats,   // (N, 8, H, W)
                       const float* __restrict__ params,       // (n_inst, 169)
                       const float* __restrict__ inst_loc,     // (n_inst, 2)
                       const float* __restrict__ soi_tab,      // (6,)
                       const int*   __restrict__ im_inds,      // (n_inst,)
                       const int*   __restrict__ fpn_levels,   // (n_inst,)
                       float*       __restrict__ out,
                       int n_inst)
{
    __shared__ float2 sp2[GI * NPARAMS];            // duplicated weights (5.4KB)
    __shared__ __align__(16) float st[H_][SW];      // strip logits (8KB)
    __shared__ float sthalo[H_];                    // left halo column (0.5KB)
    __shared__ float s_ix[GI], s_iy[GI], s_isoi[GI];
    __shared__ int   s_im[GI];

    const int tid = threadIdx.x;
    const int c0  = blockIdx.x * SW;                // first col of strip
    const int n0  = blockIdx.y * GI;                // first instance
    const int cm  = max(c0 - 1, 0);                 // halo column (clamped)

    const int g_cnt = min(GI, n_inst - n0);
    for (int i = tid; i < g_cnt * NPARAMS; i += 192) {
        float v = params[(size_t)n0 * NPARAMS + i];
        sp2[i] = make_float2(v, v);
    }
    if (tid < GI && n0 + tid < n_inst) {
        int n = n0 + tid;
        s_ix[tid]   = inst_loc[2 * n + 0];
        s_iy[tid]   = inst_loc[2 * n + 1];
        s_isoi[tid] = 1.0f / soi_tab[fpn_levels[n]];
        s_im[tid]   = im_inds[n];
    }
    __syncthreads();

    #pragma unroll 1
    for (int g = 0; g < g_cnt; g++) {
        const u64* prm = reinterpret_cast<const u64*>(sp2) + g * NPARAMS;
        const float s  = s_isoi[g];
        const float ix = s_ix[g], iy = s_iy[g];
        const float* featbase = mask_feats + (size_t)s_im[g] * IN_CH * HW_;

        // ================= compute phase: 576 units, 3 per thread ==========
        #pragma unroll 1
        for (int it = 0; it < 3; it++) {
            const int u = it * 192 + tid;
            if (u < 512) {
                // ---- main 4-px unit: row = u>>2, cols cc..cc+3 ------------
                const int row = u >> 2;
                const int cc  = c0 + ((u & 3) << 2);

                const float dx  = ix - ((float)cc * 8.0f + 4.0f);
                const float ryv = (iy - ((float)row * 8.0f + 4.0f)) * s;
                const u64 rx01 = pack2(dx * s,           (dx - 8.0f)  * s);
                const u64 rx23 = pack2((dx - 16.0f) * s, (dx - 24.0f) * s);
                const u64 ry   = pack2(ryv, ryv);

                const float4* f4 = reinterpret_cast<const float4*>(
                    featbase + (size_t)row * W_ + cc);
                u64 fp01[IN_CH], fp23[IN_CH];
                #pragma unroll
                for (int c = 0; c < IN_CH; c++) {
                    float4 v = f4[c * (HW_ / 4)];
                    fp01[c] = pack2(v.x, v.y);
                    fp23[c] = pack2(v.z, v.w);
                }

                u64 h01[CHANNELS], h23[CHANNELS];
                #pragma unroll
                for (int o = 0; o < CHANNELS; o++) {
                    u64 wx  = prm[o * 10 + 0];
                    u64 wy  = prm[o * 10 + 1];
                    u64 byy = fma2(wy, ry, prm[152 + o]);
                    u64 a0  = fma2(wx, rx01, byy);
                    u64 a1  = fma2(wx, rx23, byy);
                    #pragma unroll
                    for (int c = 0; c < IN_CH; c++) {
                        u64 w = prm[o * 10 + 2 + c];
                        a0 = fma2(w, fp01[c], a0);
                        a1 = fma2(w, fp23[c], a1);
                    }
                    h01[o] = relu2(a0);
                    h23[o] = relu2(a1);
                }

                u64 acc0 = prm[168], acc1 = prm[168];
                #pragma unroll
                for (int o = 0; o < CHANNELS; o++) {
                    u64 b1 = prm[160 + o];
                    u64 a0 = b1, a1 = b1;
                    #pragma unroll
                    for (int c = 0; c < CHANNELS; c++) {
                        u64 w = prm[80 + o * 8 + c];
                        a0 = fma2(w, h01[c], a0);
                        a1 = fma2(w, h23[c], a1);
                    }
                    u64 w2 = prm[144 + o];
                    acc0 = fma2(w2, relu2(a0), acc0);
                    acc1 = fma2(w2, relu2(a1), acc1);
                }

                float o0, o1, o2, o3;
                unpack2(acc0, o0, o1);
                unpack2(acc1, o2, o3);
                *reinterpret_cast<float4*>(&st[row][(u & 3) << 2]) =
                    make_float4(o0, o1, o2, o3);
            } else {
                // ---- halo unit: col cm, rows 2h and 2h+1 packed -----------
                const int h  = u - 512;              // 0..63
                const int r0 = 2 * h;

                const float dxh = ix - ((float)cm * 8.0f + 4.0f);
                const u64 rx = pack2(dxh * s, dxh * s);
                const u64 ry = pack2((iy - ((float)r0 * 8.0f + 4.0f)) * s,
                                     (iy - ((float)(r0 + 1) * 8.0f + 4.0f)) * s);

                const float* fb = featbase + (size_t)r0 * W_ + cm;
                u64 fp[IN_CH];
                #pragma unroll
                for (int c = 0; c < IN_CH; c++)
                    fp[c] = pack2(fb[c * HW_], fb[c * HW_ + W_]);

                u64 hh[CHANNELS];
                #pragma unroll
                for (int o = 0; o < CHANNELS; o++) {
                    u64 a = fma2(prm[o * 10 + 1], ry, prm[152 + o]);
                    a = fma2(prm[o * 10 + 0], rx, a);
                    #pragma unroll
                    for (int c = 0; c < IN_CH; c++)
                        a = fma2(prm[o * 10 + 2 + c], fp[c], a);
                    hh[o] = relu2(a);
                }
                u64 acc = prm[168];
                #pragma unroll
                for (int o = 0; o < CHANNELS; o++) {
                    u64 a = prm[160 + o];
                    #pragma unroll
                    for (int c = 0; c < CHANNELS; c++)
                        a = fma2(prm[80 + o * 8 + c], hh[c], a);
                    acc = fma2(prm[144 + o], relu2(a), acc);
                }
                float v0, v1;
                unpack2(acc, v0, v1);
                sthalo[r0]     = v0;
                sthalo[r0 + 1] = v1;
            }
        }
        __syncthreads();

        // ================= emit phase: 512 units ===========================
        float* obase = out + (size_t)(n0 + g) * (4 * HW_);
        #pragma unroll 1
        for (int it = 0; it < 3; it++) {
            const int u = it * 192 + tid;
            if (u >= 512) break;
            const int r  = u >> 2;
            const int sN = (u & 3) << 2;             // local col offset 0,4,8,12
            const int rt = (r == 0) ? 0 : r - 1;     // clamped top row

            const float4 cur = *reinterpret_cast<const float4*>(&st[r][sN]);
            const float4 top = *reinterpret_cast<const float4*>(&st[rt][sN]);
            const float left  = (sN == 0) ? sthalo[r]  : st[r][sN - 1];
            const float topL  = (sN == 0) ? sthalo[rt] : st[rt][sN - 1];

            const int cc = c0 + sN;                  // global col
            // ---- odd output row 2r+1 ----
            {
                float4 qa = make_float4(0.5f * (left + cur.x), cur.x,
                                        0.5f * (cur.x + cur.y), cur.y);
                float4 qb = make_float4(0.5f * (cur.y + cur.z), cur.z,
                                        0.5f * (cur.z + cur.w), cur.w);
                float* orow = obase + (size_t)(2 * r + 1) * (2 * W_) + 2 * cc;
                reinterpret_cast<float4*>(orow)[0] = qa;
                reinterpret_cast<float4*>(orow)[1] = qb;
            }
            // ---- even output row 2r ----
            {
                const float sL = topL  + left;
                const float s0 = top.x + cur.x;
                const float s1 = top.y + cur.y;
                const float s2 = top.z + cur.z;
                const float s3 = top.w + cur.w;
                float4 qa = make_float4(0.25f * (sL + s0), 0.5f * s0,
                                        0.25f * (s0 + s1), 0.5f * s1);
                float4 qb = make_float4(0.25f * (s1 + s2), 0.5f * s2,
                                        0.25f * (s2 + s3), 0.5f * s3);
                float* orow = obase + (size_t)(2 * r) * (2 * W_) + 2 * cc;
                reinterpret_cast<float4*>(orow)[0] = qa;
                reinterpret_cast<float4*>(orow)[1] = qb;
            }
        }
        __syncthreads();   // stage reused for next instance
    }
}

// ---------------------------------------------------------------------------
extern "C" void kernel_launch(void* const* d_in, const int* in_sizes, int n_in,
                              void* d_out, int out_size)
{
    const float* mask_feats = (const float*)d_in[0];
    const float* params     = (const float*)d_in[1];
    const float* inst_loc   = (const float*)d_in[2];
    const float* soi_tab    = (const float*)d_in[3];
    const int*   im_inds    = (const int*)d_in[4];
    const int*   fpn_levels = (const int*)d_in[5];
    float*       out        = (float*)d_out;

    const int n_inst = in_sizes[1] / NPARAMS;   // 128

    dim3 grid(W_ / SW, (n_inst + GI - 1) / GI);    // 12 x 32 = 384 blocks
    fused_mask_kernel<<<grid, 192>>>(mask_feats, params, inst_loc, soi_tab,
                                     im_inds, fpn_levels, out, n_inst);
}

// round 17
// speedup vs baseline: 1.1645x; 1.1645x over previous
#include <cuda_runtime.h>

#define CHANNELS  8
#define IN_CH     8
#define NPARAMS   169      // 80 + 64 + 8 + 8 + 8 + 1
#define H_        128
#define W_        192
#define HW_       (H_ * W_)
#define GI        4        // instances per block
#define TR        8        // logit rows per block
#define NR        (TR + 1) // + 1 recomputed halo row above

typedef unsigned long long u64;

// ---- packed fp32x2 helpers (Blackwell) -------------------------------------
__device__ __forceinline__ u64 fma2(u64 a, u64 b, u64 c) {
    u64 d;
    asm("fma.rn.f32x2 %0, %1, %2, %3;" : "=l"(d) : "l"(a), "l"(b), "l"(c));
    return d;
}
__device__ __forceinline__ u64 pack2(float lo, float hi) {
    u64 d;
    asm("mov.b64 %0, {%1, %2};" : "=l"(d) : "f"(lo), "f"(hi));
    return d;
}
__device__ __forceinline__ void unpack2(u64 v, float& lo, float& hi) {
    asm("mov.b64 {%0, %1}, %2;" : "=f"(lo), "=f"(hi) : "l"(v));
}
__device__ __forceinline__ u64 relu2(u64 v) {
    float lo, hi;
    unpack2(v, lo, hi);
    return pack2(fmaxf(lo, 0.0f), fmaxf(hi, 0.0f));
}

// ---------------------------------------------------------------------------
// Single fused kernel: MLP + full aligned-2x upsample.
// Block = 8-row tile (full width) x GI instances, 192 threads.
// Compute phase: 1728 units (GI x 9 rows x 48 strips) = 192 x 9 EXACTLY --
//   the instance loop is flattened into the unit loop for perfect balance.
//   Row 0 of each tile is the recomputed halo (logit row r0-1, clamped):
//   +12.5% fma2 over the algorithmic minimum, in exchange for deleting the
//   boundary kernel, its launch (~5.7us measured), and all g_logits traffic.
// Emit phase: 1536 units (GI x 8 rows x 48 strips) = 192 x 8 exactly; each
//   unit writes output rows 2r and 2r+1 for 4 columns (4x STG.128).
// Upsample identities (r-1, c-1 clamped at 0):
//   O[2r,  2c  ] = 0.25*(L[r-1,c-1] + L[r-1,c] + L[r,c-1] + L[r,c])
//   O[2r,  2c+1] = 0.5 *(L[r-1,c]   + L[r,c])
//   O[2r+1,2c  ] = 0.5 *(L[r,c-1]   + L[r,c])
//   O[2r+1,2c+1] =       L[r,c]
// ---------------------------------------------------------------------------
__global__ __launch_bounds__(192)
void fused_mask_kernel(const float* __restrict__ mask_feats,   // (N, 8, H, W)
                       const float* __restrict__ params,       // (n_inst, 169)
                       const float* __restrict__ inst_loc,     // (n_inst, 2)
                       const float* __restrict__ soi_tab,      // (6,)
                       const int*   __restrict__ im_inds,      // (n_inst,)
                       const int*   __restrict__ fpn_levels,   // (n_inst,)
                       float*       __restrict__ out,
                       int n_inst)
{
    __shared__ float2 sp2[GI * NPARAMS];               // duplicated weights
    __shared__ __align__(16) float st[GI][NR][W_];     // logit stage (27.6KB)
    __shared__ float s_ix[GI], s_iy[GI], s_isoi[GI];
    __shared__ int   s_im[GI];

    const int tid = threadIdx.x;
    const int r0  = blockIdx.x * TR;                   // first logit row
    const int n0  = blockIdx.y * GI;                   // first instance

    const int g_cnt = min(GI, n_inst - n0);
    for (int i = tid; i < g_cnt * NPARAMS; i += 192) {
        float v = params[(size_t)n0 * NPARAMS + i];
        sp2[i] = make_float2(v, v);
    }
    if (tid < GI && n0 + tid < n_inst) {
        int n = n0 + tid;
        s_ix[tid]   = inst_loc[2 * n + 0];
        s_iy[tid]   = inst_loc[2 * n + 1];
        s_isoi[tid] = 1.0f / soi_tab[fpn_levels[n]];
        s_im[tid]   = im_inds[n];
    }
    __syncthreads();

    // ================= compute phase: 1728 units, 9 per thread ==============
    #pragma unroll 1
    for (int it = 0; it < 9 * GI / 4; it++) {          // 9 iterations (GI=4)
        const int u    = it * 192 + tid;               // 0..1727
        const int g    = u / (NR * 48);                // instance in block
        const int rem  = u - g * (NR * 48);
        const int row  = rem / 48;                     // 0..8 (0 = halo)
        const int cc   = (rem - row * 48) * 4;         // col 0..188
        if (g >= g_cnt) break;

        const int gr = max(r0 + row - 1, 0);           // global logit row

        const u64* prm = reinterpret_cast<const u64*>(sp2) + g * NPARAMS;
        const float s  = s_isoi[g];
        const float dx  = s_ix[g] - ((float)cc * 8.0f + 4.0f);
        const float ryv = (s_iy[g] - ((float)gr * 8.0f + 4.0f)) * s;
        const u64 rx01 = pack2(dx * s,           (dx - 8.0f)  * s);
        const u64 rx23 = pack2((dx - 16.0f) * s, (dx - 24.0f) * s);
        const u64 ry   = pack2(ryv, ryv);

        const float4* f4 = reinterpret_cast<const float4*>(
            mask_feats + (size_t)s_im[g] * IN_CH * HW_ + (size_t)gr * W_ + cc);
        u64 fp01[IN_CH], fp23[IN_CH];
        #pragma unroll
        for (int c = 0; c < IN_CH; c++) {
            float4 v = f4[c * (HW_ / 4)];
            fp01[c] = pack2(v.x, v.y);
            fp23[c] = pack2(v.z, v.w);
        }

        // layer 0: 8 x 10, ReLU (byy = b + wy*ry once per output channel)
        u64 h01[CHANNELS], h23[CHANNELS];
        #pragma unroll
        for (int o = 0; o < CHANNELS; o++) {
            u64 wx  = prm[o * 10 + 0];
            u64 wy  = prm[o * 10 + 1];
            u64 byy = fma2(wy, ry, prm[152 + o]);
            u64 a0  = fma2(wx, rx01, byy);
            u64 a1  = fma2(wx, rx23, byy);
            #pragma unroll
            for (int c = 0; c < IN_CH; c++) {
                u64 w = prm[o * 10 + 2 + c];
                a0 = fma2(w, fp01[c], a0);
                a1 = fma2(w, fp23[c], a1);
            }
            h01[o] = relu2(a0);
            h23[o] = relu2(a1);
        }

        // layer 1 (ReLU) with layer 2 fused
        u64 acc0 = prm[168], acc1 = prm[168];
        #pragma unroll
        for (int o = 0; o < CHANNELS; o++) {
            u64 b1 = prm[160 + o];
            u64 a0 = b1, a1 = b1;
            #pragma unroll
            for (int c = 0; c < CHANNELS; c++) {
                u64 w = prm[80 + o * 8 + c];
                a0 = fma2(w, h01[c], a0);
                a1 = fma2(w, h23[c], a1);
            }
            u64 w2 = prm[144 + o];
            acc0 = fma2(w2, relu2(a0), acc0);
            acc1 = fma2(w2, relu2(a1), acc1);
        }

        float o0, o1, o2, o3;
        unpack2(acc0, o0, o1);
        unpack2(acc1, o2, o3);
        *reinterpret_cast<float4*>(&st[g][row][cc]) =
            make_float4(o0, o1, o2, o3);
    }
    __syncthreads();

    // ================= emit phase: 1536 units, 8 per thread ==================
    #pragma unroll 1
    for (int it = 0; it < 8; it++) {
        const int v   = it * 192 + tid;                // 0..1535
        const int g   = v / (TR * 48);
        const int rem = v - g * (TR * 48);
        const int lr  = rem / 48;                      // 0..7
        const int cc  = (rem - lr * 48) * 4;           // col 0..188
        if (g >= g_cnt) break;

        // st row i holds logit row r0 + i - 1  (i=0 is the halo)
        const float4 cur = *reinterpret_cast<const float4*>(&st[g][lr + 1][cc]);
        const float4 top = *reinterpret_cast<const float4*>(&st[g][lr][cc]);
        const float left = (cc == 0) ? cur.x : st[g][lr + 1][cc - 1];
        const float topL = (cc == 0) ? top.x : st[g][lr][cc - 1];

        const int r = r0 + lr;                         // global logit row
        float* obase = out + (size_t)(n0 + g) * (4 * HW_) + 2 * cc;

        // ---- odd output row 2r+1 (needs only row r) ----
        {
            float4 qa = make_float4(0.5f * (left + cur.x), cur.x,
                                    0.5f * (cur.x + cur.y), cur.y);
            float4 qb = make_float4(0.5f * (cur.y + cur.z), cur.z,
                                    0.5f * (cur.z + cur.w), cur.w);
            float* orow = obase + (size_t)(2 * r + 1) * (2 * W_);
            reinterpret_cast<float4*>(orow)[0] = qa;
            reinterpret_cast<float4*>(orow)[1] = qb;
        }
        // ---- even output row 2r (row r-1 = staged halo/in-tile row) ----
        {
            const float sL = topL  + left;
            const float s0 = top.x + cur.x;
            const float s1 = top.y + cur.y;
            const float s2 = top.z + cur.z;
            const float s3 = top.w + cur.w;
            float4 qa = make_float4(0.25f * (sL + s0), 0.5f * s0,
                                    0.25f * (s0 + s1), 0.5f * s1);
            float4 qb = make_float4(0.25f * (s1 + s2), 0.5f * s2,
                                    0.25f * (s2 + s3), 0.5f * s3);
            float* orow = obase + (size_t)(2 * r) * (2 * W_);
            reinterpret_cast<float4*>(orow)[0] = qa;
            reinterpret_cast<float4*>(orow)[1] = qb;
        }
    }
}

// ---------------------------------------------------------------------------
extern "C" void kernel_launch(void* const* d_in, const int* in_sizes, int n_in,
                              void* d_out, int out_size)
{
    const float* mask_feats = (const float*)d_in[0];
    const float* params     = (const float*)d_in[1];
    const float* inst_loc   = (const float*)d_in[2];
    const float* soi_tab    = (const float*)d_in[3];
    const int*   im_inds    = (const int*)d_in[4];
    const int*   fpn_levels = (const int*)d_in[5];
    float*       out        = (float*)d_out;

    const int n_inst = in_sizes[1] / NPARAMS;   // 128

    dim3 grid(H_ / TR, (n_inst + GI - 1) / GI);    // 16 x 32 = 512 blocks
    fused_mask_kernel<<<grid, 192>>>(mask_feats, params, inst_loc, soi_tab,
                                     im_inds, fpn_levels, out, n_inst);
}